// round 4
// baseline (speedup 1.0000x reference)
#include <cuda_runtime.h>
#include <cuda_bf16.h>
#include <cstdint>
#include <math.h>

// Problem constants
#define BATCH 4
#define S_LEN 2048
#define DMODEL 768
#define NHEAD 12
#define HDIM 64
#define NTOK (BATCH * S_LEN)          // 8192
#define MASK_N (NHEAD * S_LEN * S_LEN)  // 50331648 mask elements (batch dim = 1)

// Scratch (allowed: __device__ globals, no runtime allocation)
__device__ float g_q[BATCH * NHEAD * S_LEN * HDIM];   // 24MB, [b,h,s,hd]
__device__ float g_k[BATCH * NHEAD * S_LEN * HDIM];
__device__ float g_v[BATCH * NHEAD * S_LEN * HDIM];
__device__ float g_ctx[NTOK * DMODEL];                // [b,s,d]
__device__ unsigned char g_mask8[MASK_N];             // canonical 1-byte mask
__device__ int g_mask_mode;                           // 0=u8, 1=i32, 2=f32

// ---------------------------------------------------------------------------
// Mask dtype detection: inspect first 8KB of the raw buffer.
//   uint8 0/1 data  -> nonzero bytes at all offsets mod 4
//   int32 0/1 data  -> bytes at offset%4 in {1,2,3} are ALL zero
//   float32 0/1.0   -> byte%4==0 and ==1 all zero; %4 in {2,3} nonzero (0x3F80)
// ---------------------------------------------------------------------------
__global__ void detect_mask_kernel(const unsigned char* __restrict__ m)
{
    __shared__ unsigned cnt[4];
    if (threadIdx.x < 4) cnt[threadIdx.x] = 0;
    __syncthreads();
    for (int i = threadIdx.x; i < 8192; i += blockDim.x)
        if (m[i]) atomicAdd(&cnt[i & 3], 1u);
    __syncthreads();
    if (threadIdx.x == 0) {
        int mode;
        if (cnt[1] + cnt[2] + cnt[3] == 0) mode = 1;   // int32 0/1
        else if (cnt[0] > 0)               mode = 0;   // uint8
        else                               mode = 2;   // float32
        g_mask_mode = mode;
    }
}

// Repack mask into canonical uint8. One thread handles 4 elements.
__global__ void __launch_bounds__(256)
convert_mask_kernel(const void* __restrict__ mraw, unsigned char* __restrict__ out)
{
    const int mode = g_mask_mode;
    const size_t i = (size_t)blockIdx.x * blockDim.x + threadIdx.x;
    if (i >= MASK_N / 4) return;
    unsigned r;
    if (mode == 0) {
        unsigned w = ((const unsigned*)mraw)[i];
        r =  ((w         & 0xFFu) ? 0x00000001u : 0u)
          | (((w >>  8)  & 0xFFu) ? 0x00000100u : 0u)
          | (((w >> 16)  & 0xFFu) ? 0x00010000u : 0u)
          | (((w >> 24)         ) ? 0x01000000u : 0u);
    } else if (mode == 1) {
        uint4 w = ((const uint4*)mraw)[i];
        r =  (w.x ? 0x00000001u : 0u) | (w.y ? 0x00000100u : 0u)
           | (w.z ? 0x00010000u : 0u) | (w.w ? 0x01000000u : 0u);
    } else {
        float4 f = ((const float4*)mraw)[i];
        r =  (f.x != 0.f ? 0x00000001u : 0u) | (f.y != 0.f ? 0x00000100u : 0u)
           | (f.z != 0.f ? 0x00010000u : 0u) | (f.w != 0.f ? 0x01000000u : 0u);
    }
    ((unsigned*)out)[i] = r;
}

// ---------------------------------------------------------------------------
// SGEMM: C = A[M,768] @ W[768,768]^T + bias, M=8192.
// mode 0: write head-split  [b,h,s,hd]
// mode 1: write plain       [m, n]
// 128x128 tile, BK=8, 256 threads, 8x8 microtile.
// ---------------------------------------------------------------------------
__global__ void __launch_bounds__(256)
sgemm_kernel(const float* __restrict__ A, const float* __restrict__ W,
             const float* __restrict__ bias, float* __restrict__ C, int mode)
{
    __shared__ float As[8][128];
    __shared__ float Bs[8][128];

    const int tid = threadIdx.x;
    const int bm = blockIdx.y * 128;
    const int bn = blockIdx.x * 128;

    const int lr = tid >> 1;          // 0..127
    const int lc = (tid & 1) * 4;     // 0 or 4

    const int tx = tid & 15;          // 0..15
    const int ty = tid >> 4;          // 0..15

    float acc[8][8];
#pragma unroll
    for (int i = 0; i < 8; i++)
#pragma unroll
        for (int j = 0; j < 8; j++) acc[i][j] = 0.f;

    for (int k0 = 0; k0 < DMODEL; k0 += 8) {
        float4 av = *(const float4*)&A[(size_t)(bm + lr) * DMODEL + k0 + lc];
        float4 bv = *(const float4*)&W[(size_t)(bn + lr) * DMODEL + k0 + lc];
        As[lc + 0][lr] = av.x; As[lc + 1][lr] = av.y;
        As[lc + 2][lr] = av.z; As[lc + 3][lr] = av.w;
        Bs[lc + 0][lr] = bv.x; Bs[lc + 1][lr] = bv.y;
        Bs[lc + 2][lr] = bv.z; Bs[lc + 3][lr] = bv.w;
        __syncthreads();

#pragma unroll
        for (int kk = 0; kk < 8; kk++) {
            float ar[8], br[8];
            float4 a0 = *(const float4*)&As[kk][ty * 4];
            float4 a1 = *(const float4*)&As[kk][64 + ty * 4];
            float4 b0 = *(const float4*)&Bs[kk][tx * 4];
            float4 b1 = *(const float4*)&Bs[kk][64 + tx * 4];
            ar[0] = a0.x; ar[1] = a0.y; ar[2] = a0.z; ar[3] = a0.w;
            ar[4] = a1.x; ar[5] = a1.y; ar[6] = a1.z; ar[7] = a1.w;
            br[0] = b0.x; br[1] = b0.y; br[2] = b0.z; br[3] = b0.w;
            br[4] = b1.x; br[5] = b1.y; br[6] = b1.z; br[7] = b1.w;
#pragma unroll
            for (int i = 0; i < 8; i++)
#pragma unroll
                for (int j = 0; j < 8; j++)
                    acc[i][j] += ar[i] * br[j];
        }
        __syncthreads();
    }

    // Epilogue
    const int mrow[2] = { bm + ty * 4, bm + 64 + ty * 4 };
    const int ncol[2] = { bn + tx * 4, bn + 64 + tx * 4 };
#pragma unroll
    for (int ih = 0; ih < 2; ih++)
#pragma unroll
        for (int i = 0; i < 4; i++) {
            const int m = mrow[ih] + i;
#pragma unroll
            for (int jh = 0; jh < 2; jh++)
#pragma unroll
                for (int j = 0; j < 4; j++) {
                    const int n = ncol[jh] + j;
                    float v = acc[ih * 4 + i][jh * 4 + j] + bias[n];
                    if (mode == 0) {
                        const int b = m >> 11;       // /2048
                        const int s = m & 2047;
                        const int h = n >> 6;        // /64
                        const int d = n & 63;
                        C[(((size_t)b * NHEAD + h) * S_LEN + s) * HDIM + d] = v;
                    } else {
                        C[(size_t)m * DMODEL + n] = v;
                    }
                }
        }
}

// ---------------------------------------------------------------------------
// Flash attention (fp32): grid (S/128, H, B), 128 threads, 1 thread = 1 q row.
// K/V tiles of 64 rows in smem; online softmax over 16-column chunks.
// Mask consumed as canonical uint8 from g_mask8.
// ---------------------------------------------------------------------------
__global__ void __launch_bounds__(128)
flash_kernel(const float* __restrict__ Q, const float* __restrict__ K,
             const float* __restrict__ V, const unsigned char* __restrict__ mask,
             float* __restrict__ ctx)
{
    __shared__ float k_s[64 * HDIM];
    __shared__ float v_s[64 * HDIM];

    const int r  = threadIdx.x;              // 0..127
    const int qt = blockIdx.x;
    const int h  = blockIdx.y;
    const int b  = blockIdx.z;
    const int q  = qt * 128 + r;

    const size_t kvbase = ((size_t)(b * NHEAD + h)) * S_LEN * HDIM;
    const size_t mbase  = (size_t)h * S_LEN * S_LEN + (size_t)q * S_LEN;

    // q row into registers
    float qreg[HDIM];
    {
        const float* qptr = Q + kvbase + (size_t)q * HDIM;
#pragma unroll
        for (int i = 0; i < 16; i++) {
            float4 t = *(const float4*)&qptr[i * 4];
            qreg[i * 4 + 0] = t.x; qreg[i * 4 + 1] = t.y;
            qreg[i * 4 + 2] = t.z; qreg[i * 4 + 3] = t.w;
        }
    }

    float acc[HDIM];
#pragma unroll
    for (int d = 0; d < HDIM; d++) acc[d] = 0.f;
    float m_i = -INFINITY;
    float l_i = 0.f;

    for (int t = 0; t < S_LEN / 64; t++) {
        __syncthreads();
        // cooperative load of K,V 64x64 tiles
#pragma unroll
        for (int i = 0; i < 8; i++) {
            const int fid = r + i * 128;
            const int row = fid >> 4;
            const int c   = fid & 15;
            *(float4*)&k_s[row * HDIM + c * 4] =
                *(const float4*)&K[kvbase + (size_t)(t * 64 + row) * HDIM + c * 4];
            *(float4*)&v_s[row * HDIM + c * 4] =
                *(const float4*)&V[kvbase + (size_t)(t * 64 + row) * HDIM + c * 4];
        }
        __syncthreads();

#pragma unroll
        for (int c4 = 0; c4 < 4; c4++) {
            // 16 mask bytes for this chunk
            uint4 mw = *(const uint4*)&mask[mbase + t * 64 + c4 * 16];
            unsigned mb[4] = { mw.x, mw.y, mw.z, mw.w };

            float s[16];
            float cmax = -INFINITY;
#pragma unroll
            for (int j = 0; j < 16; j++) {
                const float* krow = &k_s[(c4 * 16 + j) * HDIM];
                float s0 = 0.f, s1 = 0.f, s2 = 0.f, s3 = 0.f;
#pragma unroll
                for (int d = 0; d < 16; d++) {
                    float4 kb = *(const float4*)&krow[d * 4];
                    s0 += qreg[d * 4 + 0] * kb.x;
                    s1 += qreg[d * 4 + 1] * kb.y;
                    s2 += qreg[d * 4 + 2] * kb.z;
                    s3 += qreg[d * 4 + 3] * kb.w;
                }
                float sv = ((s0 + s1) + (s2 + s3)) * 0.125f;  // 1/sqrt(64)
                unsigned byte = (mb[j >> 2] >> ((j & 3) * 8)) & 0xFFu;
                if (!byte) sv = -INFINITY;
                s[j] = sv;
                cmax = fmaxf(cmax, sv);
            }

            const float mnew = fmaxf(m_i, cmax);
            if (mnew != -INFINITY) {
                const float corr = __expf(m_i - mnew);   // m_i=-inf -> 0
                m_i = mnew;
                l_i *= corr;
#pragma unroll
                for (int d = 0; d < HDIM; d++) acc[d] *= corr;
#pragma unroll
                for (int j = 0; j < 16; j++) {
                    const float p = __expf(s[j] - mnew); // s=-inf -> 0
                    l_i += p;
                    const float* vrow = &v_s[(c4 * 16 + j) * HDIM];
#pragma unroll
                    for (int d = 0; d < 16; d++) {
                        float4 vb = *(const float4*)&vrow[d * 4];
                        acc[d * 4 + 0] += p * vb.x;
                        acc[d * 4 + 1] += p * vb.y;
                        acc[d * 4 + 2] += p * vb.z;
                        acc[d * 4 + 3] += p * vb.w;
                    }
                }
            }
        }
    }

    const float rl = (l_i > 0.f) ? (1.f / l_i) : 0.f;
    float* op = ctx + ((size_t)(b * S_LEN + q)) * DMODEL + h * HDIM;
#pragma unroll
    for (int i = 0; i < 16; i++) {
        float4 o;
        o.x = acc[i * 4 + 0] * rl;
        o.y = acc[i * 4 + 1] * rl;
        o.z = acc[i * 4 + 2] * rl;
        o.w = acc[i * 4 + 3] * rl;
        *(float4*)&op[i * 4] = o;
    }
}

// ---------------------------------------------------------------------------
extern "C" void kernel_launch(void* const* d_in, const int* in_sizes, int n_in,
                              void* d_out, int out_size)
{
    const float* hidden = (const float*)d_in[0];
    const void*  mask_raw = d_in[1];
    const float* q_w = (const float*)d_in[2];
    const float* q_b = (const float*)d_in[3];
    const float* k_w = (const float*)d_in[4];
    const float* k_b = (const float*)d_in[5];
    const float* v_w = (const float*)d_in[6];
    const float* v_b = (const float*)d_in[7];
    const float* out_w = (const float*)d_in[8];
    const float* out_b = (const float*)d_in[9];
    float* out = (float*)d_out;

    float *gq, *gk, *gv, *gctx;
    unsigned char* gmask;
    cudaGetSymbolAddress((void**)&gq,   g_q);
    cudaGetSymbolAddress((void**)&gk,   g_k);
    cudaGetSymbolAddress((void**)&gv,   g_v);
    cudaGetSymbolAddress((void**)&gctx, g_ctx);
    cudaGetSymbolAddress((void**)&gmask, g_mask8);

    // Canonicalize the mask (dtype-agnostic)
    detect_mask_kernel<<<1, 256>>>((const unsigned char*)mask_raw);
    convert_mask_kernel<<<(MASK_N / 4 + 255) / 256, 256>>>(mask_raw, gmask);

    dim3 gemmGrid(DMODEL / 128, NTOK / 128);   // (6, 64)
    dim3 gemmBlk(256);

    // QKV projections (head-split outputs)
    sgemm_kernel<<<gemmGrid, gemmBlk>>>(hidden, q_w, q_b, gq, 0);
    sgemm_kernel<<<gemmGrid, gemmBlk>>>(hidden, k_w, k_b, gk, 0);
    sgemm_kernel<<<gemmGrid, gemmBlk>>>(hidden, v_w, v_b, gv, 0);

    // Attention
    dim3 flashGrid(S_LEN / 128, NHEAD, BATCH); // (16, 12, 4)
    flash_kernel<<<flashGrid, 128>>>(gq, gk, gv, gmask, gctx);

    // Output projection (plain layout into d_out)
    sgemm_kernel<<<gemmGrid, gemmBlk>>>(gctx, out_w, out_b, out, 1);
}

// round 5
// speedup vs baseline: 2.6022x; 2.6022x over previous
#include <cuda_runtime.h>
#include <cuda_bf16.h>
#include <cstdint>
#include <math.h>

// Problem constants
#define BATCH 4
#define S_LEN 2048
#define DMODEL 768
#define NHEAD 12
#define HDIM 64
#define NTOK (BATCH * S_LEN)            // 8192
#define MASK_N (NHEAD * S_LEN * S_LEN)  // 50331648

// Scratch (allowed: __device__ globals)
__device__ __nv_bfloat16 g_qh[BATCH * NHEAD * S_LEN * HDIM];  // [b,h,s,d]
__device__ __nv_bfloat16 g_ql[BATCH * NHEAD * S_LEN * HDIM];
__device__ __nv_bfloat16 g_kh[BATCH * NHEAD * S_LEN * HDIM];  // [b,h,s,d]
__device__ __nv_bfloat16 g_kl[BATCH * NHEAD * S_LEN * HDIM];
__device__ __nv_bfloat16 g_vh[BATCH * NHEAD * HDIM * S_LEN];  // [b,h,d,s] (transposed)
__device__ __nv_bfloat16 g_vl[BATCH * NHEAD * HDIM * S_LEN];
__device__ float g_ctx[NTOK * DMODEL];                         // [b,s,d]
__device__ unsigned char g_mask8[MASK_N];
__device__ int g_mask_mode;

// ---------------------------------------------------------------------------
// Mask dtype detection (same as passing R4 kernel)
// ---------------------------------------------------------------------------
__global__ void detect_mask_kernel(const unsigned char* __restrict__ m)
{
    __shared__ unsigned cnt[4];
    if (threadIdx.x < 4) cnt[threadIdx.x] = 0;
    __syncthreads();
    for (int i = threadIdx.x; i < 8192; i += blockDim.x)
        if (m[i]) atomicAdd(&cnt[i & 3], 1u);
    __syncthreads();
    if (threadIdx.x == 0) {
        int mode;
        if (cnt[1] + cnt[2] + cnt[3] == 0) mode = 1;   // int32 0/1
        else if (cnt[0] > 0)               mode = 0;   // uint8
        else                               mode = 2;   // float32
        g_mask_mode = mode;
    }
}

__global__ void __launch_bounds__(256)
convert_mask_kernel(const void* __restrict__ mraw, unsigned char* __restrict__ out)
{
    const int mode = g_mask_mode;
    const size_t i = (size_t)blockIdx.x * blockDim.x + threadIdx.x;
    if (i >= MASK_N / 4) return;
    unsigned r;
    if (mode == 0) {
        unsigned w = ((const unsigned*)mraw)[i];
        r =  ((w         & 0xFFu) ? 0x00000001u : 0u)
          | (((w >>  8)  & 0xFFu) ? 0x00000100u : 0u)
          | (((w >> 16)  & 0xFFu) ? 0x00010000u : 0u)
          | (((w >> 24)         ) ? 0x01000000u : 0u);
    } else if (mode == 1) {
        uint4 w = ((const uint4*)mraw)[i];
        r =  (w.x ? 0x00000001u : 0u) | (w.y ? 0x00000100u : 0u)
           | (w.z ? 0x00010000u : 0u) | (w.w ? 0x01000000u : 0u);
    } else {
        float4 f = ((const float4*)mraw)[i];
        r =  (f.x != 0.f ? 0x00000001u : 0u) | (f.y != 0.f ? 0x00000100u : 0u)
           | (f.z != 0.f ? 0x00010000u : 0u) | (f.w != 0.f ? 0x01000000u : 0u);
    }
    ((unsigned*)out)[i] = r;
}

// ---------------------------------------------------------------------------
// SGEMM: C = A[8192,768] @ W[768,768]^T + bias.
// mode 0: head-split bf16 hi/lo  [b,h,s,d]
// mode 1: plain fp32             [m,n]
// mode 2: head-split TRANSPOSED bf16 hi/lo [b,h,d,s]  (for V)
// ---------------------------------------------------------------------------
__global__ void __launch_bounds__(256)
sgemm_kernel(const float* __restrict__ A, const float* __restrict__ W,
             const float* __restrict__ bias, float* __restrict__ Cf,
             __nv_bfloat16* __restrict__ CH, __nv_bfloat16* __restrict__ CL,
             int mode)
{
    __shared__ float As[8][128];
    __shared__ float Bs[8][128];

    const int tid = threadIdx.x;
    const int bm = blockIdx.y * 128;
    const int bn = blockIdx.x * 128;

    const int lr = tid >> 1;
    const int lc = (tid & 1) * 4;
    const int tx = tid & 15;
    const int ty = tid >> 4;

    float acc[8][8];
#pragma unroll
    for (int i = 0; i < 8; i++)
#pragma unroll
        for (int j = 0; j < 8; j++) acc[i][j] = 0.f;

    for (int k0 = 0; k0 < DMODEL; k0 += 8) {
        float4 av = *(const float4*)&A[(size_t)(bm + lr) * DMODEL + k0 + lc];
        float4 bv = *(const float4*)&W[(size_t)(bn + lr) * DMODEL + k0 + lc];
        As[lc + 0][lr] = av.x; As[lc + 1][lr] = av.y;
        As[lc + 2][lr] = av.z; As[lc + 3][lr] = av.w;
        Bs[lc + 0][lr] = bv.x; Bs[lc + 1][lr] = bv.y;
        Bs[lc + 2][lr] = bv.z; Bs[lc + 3][lr] = bv.w;
        __syncthreads();

#pragma unroll
        for (int kk = 0; kk < 8; kk++) {
            float ar[8], br[8];
            float4 a0 = *(const float4*)&As[kk][ty * 4];
            float4 a1 = *(const float4*)&As[kk][64 + ty * 4];
            float4 b0 = *(const float4*)&Bs[kk][tx * 4];
            float4 b1 = *(const float4*)&Bs[kk][64 + tx * 4];
            ar[0] = a0.x; ar[1] = a0.y; ar[2] = a0.z; ar[3] = a0.w;
            ar[4] = a1.x; ar[5] = a1.y; ar[6] = a1.z; ar[7] = a1.w;
            br[0] = b0.x; br[1] = b0.y; br[2] = b0.z; br[3] = b0.w;
            br[4] = b1.x; br[5] = b1.y; br[6] = b1.z; br[7] = b1.w;
#pragma unroll
            for (int i = 0; i < 8; i++)
#pragma unroll
                for (int j = 0; j < 8; j++)
                    acc[i][j] += ar[i] * br[j];
        }
        __syncthreads();
    }

    const int mrow[2] = { bm + ty * 4, bm + 64 + ty * 4 };
    const int ncol[2] = { bn + tx * 4, bn + 64 + tx * 4 };
#pragma unroll
    for (int ih = 0; ih < 2; ih++)
#pragma unroll
        for (int i = 0; i < 4; i++) {
            const int m = mrow[ih] + i;
#pragma unroll
            for (int jh = 0; jh < 2; jh++)
#pragma unroll
                for (int j = 0; j < 4; j++) {
                    const int n = ncol[jh] + j;
                    float v = acc[ih * 4 + i][jh * 4 + j] + bias[n];
                    if (mode == 1) {
                        Cf[(size_t)m * DMODEL + n] = v;
                    } else {
                        const int b = m >> 11;
                        const int s = m & 2047;
                        const int h = n >> 6;
                        const int d = n & 63;
                        __nv_bfloat16 hi = __float2bfloat16(v);
                        __nv_bfloat16 lo = __float2bfloat16(v - __bfloat162float(hi));
                        size_t idx;
                        if (mode == 0)
                            idx = (((size_t)b * NHEAD + h) * S_LEN + s) * HDIM + d;
                        else
                            idx = (((size_t)b * NHEAD + h) * HDIM + d) * S_LEN + s;
                        CH[idx] = hi;
                        CL[idx] = lo;
                    }
                }
        }
}

// ---------------------------------------------------------------------------
// mma.sync m16n8k16 bf16 helper (f32 accumulate)
// ---------------------------------------------------------------------------
__device__ __forceinline__ void mma_bf16(float* c, const unsigned* a, const unsigned* b)
{
    asm volatile(
        "mma.sync.aligned.m16n8k16.row.col.f32.bf16.bf16.f32 "
        "{%0,%1,%2,%3},{%4,%5,%6,%7},{%8,%9},{%0,%1,%2,%3};"
        : "+f"(c[0]), "+f"(c[1]), "+f"(c[2]), "+f"(c[3])
        : "r"(a[0]), "r"(a[1]), "r"(a[2]), "r"(a[3]),
          "r"(b[0]), "r"(b[1]));
}

__device__ __forceinline__ unsigned pack_bf16x2(float x, float y)
{
    __nv_bfloat162 t = __float22bfloat162_rn(make_float2(x, y));
    return *(unsigned*)&t;
}

#define MASKVAL (-1e30f)

// ---------------------------------------------------------------------------
// Flash attention via tensor-core MMA.
// grid (S/64, H, B), 128 threads (4 warps, 16 q-rows each).
// QK^T = qh*kh + qh*kl + ql*kh ;  PV = p*vh + p*vl  (p bf16)
// ---------------------------------------------------------------------------
__global__ void __launch_bounds__(128)
flash_mma_kernel(const __nv_bfloat16* __restrict__ qh, const __nv_bfloat16* __restrict__ ql,
                 const __nv_bfloat16* __restrict__ kh, const __nv_bfloat16* __restrict__ kl,
                 const __nv_bfloat16* __restrict__ vh, const __nv_bfloat16* __restrict__ vl,
                 const unsigned char* __restrict__ mask, float* __restrict__ ctx)
{
    __shared__ __nv_bfloat16 kh_s[64][72];
    __shared__ __nv_bfloat16 kl_s[64][72];
    __shared__ __nv_bfloat16 vh_s[64][72];   // [d][kcol]
    __shared__ __nv_bfloat16 vl_s[64][72];
    __shared__ unsigned char m_s[64][64];

    const int tid  = threadIdx.x;
    const int w    = tid >> 5;
    const int lane = tid & 31;
    const int g    = lane >> 2;
    const int t2   = (lane & 3) * 2;
    const int qt = blockIdx.x, h = blockIdx.y, b = blockIdx.z;
    const int qbase = qt * 64;
    const int wq = w * 16;

    const size_t bh   = (size_t)(b * NHEAD + h);
    const size_t kvb  = bh * S_LEN * HDIM;   // [s][d]
    const size_t vtb  = bh * HDIM * S_LEN;   // [d][s]
    const size_t mrb  = (size_t)h * S_LEN * S_LEN;

    // Q fragments (hi & lo): 4 k-frags x 4 regs
    unsigned qfh[4][4], qfl[4][4];
    {
        const size_t r0 = (size_t)(qbase + wq + g) * HDIM;
        const size_t r1 = r0 + 8 * HDIM;
        const __nv_bfloat16* ph = qh + kvb;
        const __nv_bfloat16* pl = ql + kvb;
#pragma unroll
        for (int kf = 0; kf < 4; kf++) {
            int c0 = kf * 16 + t2, c1 = c0 + 8;
            qfh[kf][0] = *(const unsigned*)&ph[r0 + c0];
            qfh[kf][1] = *(const unsigned*)&ph[r1 + c0];
            qfh[kf][2] = *(const unsigned*)&ph[r0 + c1];
            qfh[kf][3] = *(const unsigned*)&ph[r1 + c1];
            qfl[kf][0] = *(const unsigned*)&pl[r0 + c0];
            qfl[kf][1] = *(const unsigned*)&pl[r1 + c0];
            qfl[kf][2] = *(const unsigned*)&pl[r0 + c1];
            qfl[kf][3] = *(const unsigned*)&pl[r1 + c1];
        }
    }

    float o[8][4];
#pragma unroll
    for (int nt = 0; nt < 8; nt++)
#pragma unroll
        for (int i = 0; i < 4; i++) o[nt][i] = 0.f;
    float m0r = MASKVAL, m1r = MASKVAL;
    float l0 = 0.f, l1 = 0.f;

    for (int kt = 0; kt < S_LEN / 64; kt++) {
        __syncthreads();
        // K/V tiles: 64 rows x 128B each; 512 16B-chunks; 128 threads -> 4 iters
#pragma unroll
        for (int it = 0; it < 4; it++) {
            int fid = tid + it * 128;
            int row = fid >> 3, c = fid & 7;
            *(uint4*)&kh_s[row][c * 8] =
                *(const uint4*)&kh[kvb + (size_t)(kt * 64 + row) * HDIM + c * 8];
            *(uint4*)&kl_s[row][c * 8] =
                *(const uint4*)&kl[kvb + (size_t)(kt * 64 + row) * HDIM + c * 8];
            *(uint4*)&vh_s[row][c * 8] =
                *(const uint4*)&vh[vtb + (size_t)row * S_LEN + kt * 64 + c * 8];
            *(uint4*)&vl_s[row][c * 8] =
                *(const uint4*)&vl[vtb + (size_t)row * S_LEN + kt * 64 + c * 8];
        }
        // mask tile: 64 x 64B
#pragma unroll
        for (int it = 0; it < 2; it++) {
            int fid = tid + it * 128;
            int row = fid >> 2, c = fid & 3;
            *(uint4*)&m_s[row][c * 16] =
                *(const uint4*)&mask[mrb + (size_t)(qbase + row) * S_LEN + kt * 64 + c * 16];
        }
        __syncthreads();

        // ---- S = Q K^T (hi/lo, 3 MMAs per frag pair) ----
        float sacc[8][4];
#pragma unroll
        for (int nt = 0; nt < 8; nt++)
#pragma unroll
            for (int i = 0; i < 4; i++) sacc[nt][i] = 0.f;

#pragma unroll
        for (int nt = 0; nt < 8; nt++) {
            const int nr = nt * 8 + g;
#pragma unroll
            for (int kf = 0; kf < 4; kf++) {
                const int col = kf * 16 + t2;
                unsigned bhf[2], blf[2];
                bhf[0] = *(const unsigned*)&kh_s[nr][col];
                bhf[1] = *(const unsigned*)&kh_s[nr][col + 8];
                blf[0] = *(const unsigned*)&kl_s[nr][col];
                blf[1] = *(const unsigned*)&kl_s[nr][col + 8];
                mma_bf16(sacc[nt], qfh[kf], bhf);
                mma_bf16(sacc[nt], qfh[kf], blf);
                mma_bf16(sacc[nt], qfl[kf], bhf);
            }
        }

        // ---- scale + mask ----
#pragma unroll
        for (int nt = 0; nt < 8; nt++) {
            unsigned short mm0 = *(const unsigned short*)&m_s[wq + g][nt * 8 + t2];
            unsigned short mm1 = *(const unsigned short*)&m_s[wq + g + 8][nt * 8 + t2];
            sacc[nt][0] = (mm0 & 0xFF) ? sacc[nt][0] * 0.125f : MASKVAL;
            sacc[nt][1] = (mm0 >> 8)   ? sacc[nt][1] * 0.125f : MASKVAL;
            sacc[nt][2] = (mm1 & 0xFF) ? sacc[nt][2] * 0.125f : MASKVAL;
            sacc[nt][3] = (mm1 >> 8)   ? sacc[nt][3] * 0.125f : MASKVAL;
        }

        // ---- online softmax ----
        float mx0 = MASKVAL, mx1 = MASKVAL;
#pragma unroll
        for (int nt = 0; nt < 8; nt++) {
            mx0 = fmaxf(mx0, fmaxf(sacc[nt][0], sacc[nt][1]));
            mx1 = fmaxf(mx1, fmaxf(sacc[nt][2], sacc[nt][3]));
        }
        mx0 = fmaxf(mx0, __shfl_xor_sync(0xffffffffu, mx0, 1));
        mx0 = fmaxf(mx0, __shfl_xor_sync(0xffffffffu, mx0, 2));
        mx1 = fmaxf(mx1, __shfl_xor_sync(0xffffffffu, mx1, 1));
        mx1 = fmaxf(mx1, __shfl_xor_sync(0xffffffffu, mx1, 2));

        const float mn0 = fmaxf(m0r, mx0);
        const float mn1 = fmaxf(m1r, mx1);
        const float corr0 = __expf(m0r - mn0);
        const float corr1 = __expf(m1r - mn1);
        m0r = mn0; m1r = mn1;
        l0 *= corr0; l1 *= corr1;
#pragma unroll
        for (int nt = 0; nt < 8; nt++) {
            o[nt][0] *= corr0; o[nt][1] *= corr0;
            o[nt][2] *= corr1; o[nt][3] *= corr1;
        }

        unsigned pfrag[8][2];
#pragma unroll
        for (int nt = 0; nt < 8; nt++) {
            float p0 = __expf(sacc[nt][0] - mn0);
            float p1 = __expf(sacc[nt][1] - mn0);
            float p2 = __expf(sacc[nt][2] - mn1);
            float p3 = __expf(sacc[nt][3] - mn1);
            l0 += p0 + p1;
            l1 += p2 + p3;
            pfrag[nt][0] = pack_bf16x2(p0, p1);
            pfrag[nt][1] = pack_bf16x2(p2, p3);
        }

        // ---- O += P V ----
#pragma unroll
        for (int nt = 0; nt < 8; nt++) {
            const int nr = nt * 8 + g;
#pragma unroll
            for (int kf = 0; kf < 4; kf++) {
                unsigned a[4] = { pfrag[2 * kf][0], pfrag[2 * kf][1],
                                  pfrag[2 * kf + 1][0], pfrag[2 * kf + 1][1] };
                const int col = kf * 16 + t2;
                unsigned bvh[2], bvl[2];
                bvh[0] = *(const unsigned*)&vh_s[nr][col];
                bvh[1] = *(const unsigned*)&vh_s[nr][col + 8];
                bvl[0] = *(const unsigned*)&vl_s[nr][col];
                bvl[1] = *(const unsigned*)&vl_s[nr][col + 8];
                mma_bf16(o[nt], a, bvh);
                mma_bf16(o[nt], a, bvl);
            }
        }
    }

    // ---- finalize ----
    l0 += __shfl_xor_sync(0xffffffffu, l0, 1);
    l0 += __shfl_xor_sync(0xffffffffu, l0, 2);
    l1 += __shfl_xor_sync(0xffffffffu, l1, 1);
    l1 += __shfl_xor_sync(0xffffffffu, l1, 2);
    const float rl0 = (l0 > 0.f) ? (1.f / l0) : 0.f;
    const float rl1 = (l1 > 0.f) ? (1.f / l1) : 0.f;

    const int qr0 = qbase + wq + g;
    float* base0 = ctx + ((size_t)b * S_LEN + qr0) * DMODEL + h * HDIM;
    float* base1 = base0 + (size_t)8 * DMODEL;
#pragma unroll
    for (int nt = 0; nt < 8; nt++) {
        float2 v0 = { o[nt][0] * rl0, o[nt][1] * rl0 };
        float2 v1 = { o[nt][2] * rl1, o[nt][3] * rl1 };
        *(float2*)&base0[nt * 8 + t2] = v0;
        *(float2*)&base1[nt * 8 + t2] = v1;
    }
}

// ---------------------------------------------------------------------------
extern "C" void kernel_launch(void* const* d_in, const int* in_sizes, int n_in,
                              void* d_out, int out_size)
{
    const float* hidden = (const float*)d_in[0];
    const void*  mask_raw = d_in[1];
    const float* q_w = (const float*)d_in[2];
    const float* q_b = (const float*)d_in[3];
    const float* k_w = (const float*)d_in[4];
    const float* k_b = (const float*)d_in[5];
    const float* v_w = (const float*)d_in[6];
    const float* v_b = (const float*)d_in[7];
    const float* out_w = (const float*)d_in[8];
    const float* out_b = (const float*)d_in[9];
    float* out = (float*)d_out;

    __nv_bfloat16 *gqh, *gql, *gkh, *gkl, *gvh, *gvl;
    float* gctx;
    unsigned char* gmask;
    cudaGetSymbolAddress((void**)&gqh, g_qh);
    cudaGetSymbolAddress((void**)&gql, g_ql);
    cudaGetSymbolAddress((void**)&gkh, g_kh);
    cudaGetSymbolAddress((void**)&gkl, g_kl);
    cudaGetSymbolAddress((void**)&gvh, g_vh);
    cudaGetSymbolAddress((void**)&gvl, g_vl);
    cudaGetSymbolAddress((void**)&gctx, g_ctx);
    cudaGetSymbolAddress((void**)&gmask, g_mask8);

    // Canonicalize mask
    detect_mask_kernel<<<1, 256>>>((const unsigned char*)mask_raw);
    convert_mask_kernel<<<(MASK_N / 4 + 255) / 256, 256>>>(mask_raw, gmask);

    dim3 gemmGrid(DMODEL / 128, NTOK / 128);
    dim3 gemmBlk(256);

    // QKV projections -> bf16 hi/lo (V transposed)
    sgemm_kernel<<<gemmGrid, gemmBlk>>>(hidden, q_w, q_b, nullptr, gqh, gql, 0);
    sgemm_kernel<<<gemmGrid, gemmBlk>>>(hidden, k_w, k_b, nullptr, gkh, gkl, 0);
    sgemm_kernel<<<gemmGrid, gemmBlk>>>(hidden, v_w, v_b, nullptr, gvh, gvl, 2);

    // Flash attention on tensor cores
    dim3 flashGrid(S_LEN / 64, NHEAD, BATCH);  // (32, 12, 4)
    flash_mma_kernel<<<flashGrid, 128>>>(gqh, gql, gkh, gkl, gvh, gvl, gmask, gctx);

    // Output projection (fp32)
    sgemm_kernel<<<gemmGrid, gemmBlk>>>(gctx, out_w, out_b, out, nullptr, nullptr, 1);
}

// round 6
// speedup vs baseline: 4.2582x; 1.6364x over previous
#include <cuda_runtime.h>
#include <cuda_bf16.h>
#include <cstdint>
#include <math.h>

// Problem constants
#define BATCH 4
#define S_LEN 2048
#define DMODEL 768
#define NHEAD 12
#define HDIM 64
#define NTOK (BATCH * S_LEN)            // 8192
#define MASK_N (NHEAD * S_LEN * S_LEN)  // 50331648

// -------------------- scratch (__device__ globals) -------------------------
__device__ __nv_bfloat16 g_hh[NTOK * DMODEL];   // hidden hi
__device__ __nv_bfloat16 g_hl[NTOK * DMODEL];   // hidden lo
__device__ __nv_bfloat16 g_wh[4][DMODEL * DMODEL]; // q,k,v,out weight hi
__device__ __nv_bfloat16 g_wl[4][DMODEL * DMODEL]; // lo
__device__ __nv_bfloat16 g_qh[BATCH * NHEAD * S_LEN * HDIM];  // [b,h,s,d]
__device__ __nv_bfloat16 g_ql[BATCH * NHEAD * S_LEN * HDIM];
__device__ __nv_bfloat16 g_kh[BATCH * NHEAD * S_LEN * HDIM];
__device__ __nv_bfloat16 g_kl[BATCH * NHEAD * S_LEN * HDIM];
__device__ __nv_bfloat16 g_vh[BATCH * NHEAD * HDIM * S_LEN];  // [b,h,d,s]
__device__ __nv_bfloat16 g_vl[BATCH * NHEAD * HDIM * S_LEN];
__device__ __nv_bfloat16 g_ch[NTOK * DMODEL];   // ctx hi  [b,s,d]
__device__ __nv_bfloat16 g_cl[NTOK * DMODEL];   // ctx lo
__device__ unsigned char g_mask8[MASK_N];
__device__ int g_mask_mode;

// ---------------------------------------------------------------------------
// Mask dtype detection + canonicalization (proven in R4/R5)
// ---------------------------------------------------------------------------
__global__ void detect_mask_kernel(const unsigned char* __restrict__ m)
{
    __shared__ unsigned cnt[4];
    if (threadIdx.x < 4) cnt[threadIdx.x] = 0;
    __syncthreads();
    for (int i = threadIdx.x; i < 8192; i += blockDim.x)
        if (m[i]) atomicAdd(&cnt[i & 3], 1u);
    __syncthreads();
    if (threadIdx.x == 0) {
        int mode;
        if (cnt[1] + cnt[2] + cnt[3] == 0) mode = 1;   // int32 0/1
        else if (cnt[0] > 0)               mode = 0;   // uint8
        else                               mode = 2;   // float32
        g_mask_mode = mode;
    }
}

__global__ void __launch_bounds__(256)
convert_mask_kernel(const void* __restrict__ mraw, unsigned char* __restrict__ out)
{
    const int mode = g_mask_mode;
    const size_t i = (size_t)blockIdx.x * blockDim.x + threadIdx.x;
    if (i >= MASK_N / 4) return;
    unsigned r;
    if (mode == 0) {
        unsigned w = ((const unsigned*)mraw)[i];
        r =  ((w         & 0xFFu) ? 0x00000001u : 0u)
          | (((w >>  8)  & 0xFFu) ? 0x00000100u : 0u)
          | (((w >> 16)  & 0xFFu) ? 0x00010000u : 0u)
          | (((w >> 24)         ) ? 0x01000000u : 0u);
    } else if (mode == 1) {
        uint4 w = ((const uint4*)mraw)[i];
        r =  (w.x ? 0x00000001u : 0u) | (w.y ? 0x00000100u : 0u)
           | (w.z ? 0x00010000u : 0u) | (w.w ? 0x01000000u : 0u);
    } else {
        float4 f = ((const float4*)mraw)[i];
        r =  (f.x != 0.f ? 0x00000001u : 0u) | (f.y != 0.f ? 0x00000100u : 0u)
           | (f.z != 0.f ? 0x00010000u : 0u) | (f.w != 0.f ? 0x01000000u : 0u);
    }
    ((unsigned*)out)[i] = r;
}

// ---------------------------------------------------------------------------
// fp32 -> bf16 hi/lo split, 4 elems per thread
// ---------------------------------------------------------------------------
__device__ __forceinline__ unsigned pack_bf16x2(float x, float y)
{
    __nv_bfloat162 t = __float22bfloat162_rn(make_float2(x, y));
    return *(unsigned*)&t;
}

__global__ void __launch_bounds__(256)
cvt_hilo_kernel(const float* __restrict__ x, __nv_bfloat16* __restrict__ h,
                __nv_bfloat16* __restrict__ l, int n4)
{
    const int i = blockIdx.x * blockDim.x + threadIdx.x;
    if (i >= n4) return;
    float4 v = ((const float4*)x)[i];
    float h0 = __bfloat162float(__float2bfloat16(v.x));
    float h1 = __bfloat162float(__float2bfloat16(v.y));
    float h2 = __bfloat162float(__float2bfloat16(v.z));
    float h3 = __bfloat162float(__float2bfloat16(v.w));
    uint2 ph = { pack_bf16x2(h0, h1), pack_bf16x2(h2, h3) };
    uint2 pl = { pack_bf16x2(v.x - h0, v.y - h1), pack_bf16x2(v.z - h2, v.w - h3) };
    ((uint2*)h)[i] = ph;
    ((uint2*)l)[i] = pl;
}

// ---------------------------------------------------------------------------
// mma.sync m16n8k16 bf16 helper (f32 accumulate)
// ---------------------------------------------------------------------------
__device__ __forceinline__ void mma_bf16(float* c, const unsigned* a, const unsigned* b)
{
    asm volatile(
        "mma.sync.aligned.m16n8k16.row.col.f32.bf16.bf16.f32 "
        "{%0,%1,%2,%3},{%4,%5,%6,%7},{%8,%9},{%0,%1,%2,%3};"
        : "+f"(c[0]), "+f"(c[1]), "+f"(c[2]), "+f"(c[3])
        : "r"(a[0]), "r"(a[1]), "r"(a[2]), "r"(a[3]),
          "r"(b[0]), "r"(b[1]));
}

// ---------------------------------------------------------------------------
// Tensor-core GEMM: C = A[8192,768] @ W[768,768]^T + bias, hi/lo bf16 inputs.
// A, W given as (hi, lo); C = Ah*Wh + Ah*Wl + Al*Wh  (fp32 accum).
// mode 0: head-split bf16 hi/lo  [b,h,s,d]
// mode 1: plain fp32             [m,n]
// mode 2: head-split transposed bf16 hi/lo [b,h,d,s]
// Block 256 thr = 8 warps (2x4), CTA tile 128x128, warp tile 64x32, BK=32.
// ---------------------------------------------------------------------------
__global__ void __launch_bounds__(256)
mma_gemm_kernel(const __nv_bfloat16* __restrict__ Ah, const __nv_bfloat16* __restrict__ Al,
                const __nv_bfloat16* __restrict__ Wh, const __nv_bfloat16* __restrict__ Wl,
                const float* __restrict__ bias, float* __restrict__ Cf,
                __nv_bfloat16* __restrict__ CH, __nv_bfloat16* __restrict__ CL,
                int mode)
{
    __shared__ __nv_bfloat16 Ahs[128][40];
    __shared__ __nv_bfloat16 Als[128][40];
    __shared__ __nv_bfloat16 Whs[128][40];
    __shared__ __nv_bfloat16 Wls[128][40];

    const int tid  = threadIdx.x;
    const int w    = tid >> 5;
    const int lane = tid & 31;
    const int g    = lane >> 2;
    const int t2   = (lane & 3) * 2;
    const int wm   = w >> 2;          // 0..1
    const int wn   = w & 3;           // 0..3
    const int bm = blockIdx.y * 128;
    const int bn = blockIdx.x * 128;

    float c[16][4];                   // [mf*4+nf]
#pragma unroll
    for (int i = 0; i < 16; i++)
#pragma unroll
        for (int j = 0; j < 4; j++) c[i][j] = 0.f;

    for (int k0 = 0; k0 < DMODEL; k0 += 32) {
        // each array: 128 rows x 32 cols bf16 = 512 16B chunks; 256 thr -> 2 each
#pragma unroll
        for (int it = 0; it < 2; it++) {
            int fid = tid + it * 256;
            int row = fid >> 2, cc = (fid & 3) * 8;
            *(uint4*)&Ahs[row][cc] = *(const uint4*)&Ah[(size_t)(bm + row) * DMODEL + k0 + cc];
            *(uint4*)&Als[row][cc] = *(const uint4*)&Al[(size_t)(bm + row) * DMODEL + k0 + cc];
            *(uint4*)&Whs[row][cc] = *(const uint4*)&Wh[(size_t)(bn + row) * DMODEL + k0 + cc];
            *(uint4*)&Wls[row][cc] = *(const uint4*)&Wl[(size_t)(bn + row) * DMODEL + k0 + cc];
        }
        __syncthreads();

#pragma unroll
        for (int kf = 0; kf < 2; kf++) {
            const int col = kf * 16 + t2;
            unsigned ah[4][4], al[4][4];
#pragma unroll
            for (int mf = 0; mf < 4; mf++) {
                const int r0 = wm * 64 + mf * 16 + g;
                ah[mf][0] = *(const unsigned*)&Ahs[r0][col];
                ah[mf][1] = *(const unsigned*)&Ahs[r0 + 8][col];
                ah[mf][2] = *(const unsigned*)&Ahs[r0][col + 8];
                ah[mf][3] = *(const unsigned*)&Ahs[r0 + 8][col + 8];
                al[mf][0] = *(const unsigned*)&Als[r0][col];
                al[mf][1] = *(const unsigned*)&Als[r0 + 8][col];
                al[mf][2] = *(const unsigned*)&Als[r0][col + 8];
                al[mf][3] = *(const unsigned*)&Als[r0 + 8][col + 8];
            }
            unsigned bh_[4][2], bl_[4][2];
#pragma unroll
            for (int nf = 0; nf < 4; nf++) {
                const int n0 = wn * 32 + nf * 8 + g;
                bh_[nf][0] = *(const unsigned*)&Whs[n0][col];
                bh_[nf][1] = *(const unsigned*)&Whs[n0][col + 8];
                bl_[nf][0] = *(const unsigned*)&Wls[n0][col];
                bl_[nf][1] = *(const unsigned*)&Wls[n0][col + 8];
            }
#pragma unroll
            for (int mf = 0; mf < 4; mf++)
#pragma unroll
                for (int nf = 0; nf < 4; nf++) {
                    mma_bf16(c[mf * 4 + nf], ah[mf], bh_[nf]);
                    mma_bf16(c[mf * 4 + nf], ah[mf], bl_[nf]);
                    mma_bf16(c[mf * 4 + nf], al[mf], bh_[nf]);
                }
        }
        __syncthreads();
    }

    // epilogue
#pragma unroll
    for (int mf = 0; mf < 4; mf++) {
#pragma unroll
        for (int nf = 0; nf < 4; nf++) {
            const int colb = bn + wn * 32 + nf * 8 + t2;
            const float b0 = bias[colb], b1 = bias[colb + 1];
            float v[4] = { c[mf * 4 + nf][0] + b0, c[mf * 4 + nf][1] + b1,
                           c[mf * 4 + nf][2] + b0, c[mf * 4 + nf][3] + b1 };
#pragma unroll
            for (int half = 0; half < 2; half++) {
                const int m = bm + wm * 64 + mf * 16 + g + half * 8;
                const float x0 = v[half * 2], x1 = v[half * 2 + 1];
                if (mode == 1) {
                    float2 p = { x0, x1 };
                    *(float2*)&Cf[(size_t)m * DMODEL + colb] = p;
                } else {
                    const int b = m >> 11;
                    const int s = m & 2047;
                    const int h = colb >> 6;
                    const int d = colb & 63;
                    float h0 = __bfloat162float(__float2bfloat16(x0));
                    float h1 = __bfloat162float(__float2bfloat16(x1));
                    if (mode == 0) {
                        size_t idx = (((size_t)b * NHEAD + h) * S_LEN + s) * HDIM + d;
                        *(unsigned*)&CH[idx] = pack_bf16x2(h0, h1);
                        *(unsigned*)&CL[idx] = pack_bf16x2(x0 - h0, x1 - h1);
                    } else { // mode 2: [b,h,d,s]
                        size_t base = (((size_t)b * NHEAD + h) * HDIM + d) * S_LEN + s;
                        CH[base] = __float2bfloat16(h0);
                        CL[base] = __float2bfloat16(x0 - h0);
                        CH[base + S_LEN] = __float2bfloat16(h1);
                        CL[base + S_LEN] = __float2bfloat16(x1 - h1);
                    }
                }
            }
        }
    }
}

#define MASKVAL (-1e30f)

// ---------------------------------------------------------------------------
// Flash attention via tensor-core MMA (hi/lo QK^T, hi/lo PV).
// grid (S/64, H, B), 128 threads (4 warps, 16 q-rows each).
// Writes ctx as bf16 hi/lo directly.
// ---------------------------------------------------------------------------
__global__ void __launch_bounds__(128)
flash_mma_kernel(const __nv_bfloat16* __restrict__ qh, const __nv_bfloat16* __restrict__ ql,
                 const __nv_bfloat16* __restrict__ kh, const __nv_bfloat16* __restrict__ kl,
                 const __nv_bfloat16* __restrict__ vh, const __nv_bfloat16* __restrict__ vl,
                 const unsigned char* __restrict__ mask,
                 __nv_bfloat16* __restrict__ ch, __nv_bfloat16* __restrict__ cl)
{
    __shared__ __nv_bfloat16 kh_s[64][72];
    __shared__ __nv_bfloat16 kl_s[64][72];
    __shared__ __nv_bfloat16 vh_s[64][72];   // [d][kcol]
    __shared__ __nv_bfloat16 vl_s[64][72];
    __shared__ unsigned char m_s[64][64];

    const int tid  = threadIdx.x;
    const int w    = tid >> 5;
    const int lane = tid & 31;
    const int g    = lane >> 2;
    const int t2   = (lane & 3) * 2;
    const int qt = blockIdx.x, h = blockIdx.y, b = blockIdx.z;
    const int qbase = qt * 64;
    const int wq = w * 16;

    const size_t bh   = (size_t)(b * NHEAD + h);
    const size_t kvb  = bh * S_LEN * HDIM;
    const size_t vtb  = bh * HDIM * S_LEN;
    const size_t mrb  = (size_t)h * S_LEN * S_LEN;

    unsigned qfh[4][4], qfl[4][4];
    {
        const size_t r0 = (size_t)(qbase + wq + g) * HDIM;
        const size_t r1 = r0 + 8 * HDIM;
        const __nv_bfloat16* ph = qh + kvb;
        const __nv_bfloat16* pl = ql + kvb;
#pragma unroll
        for (int kf = 0; kf < 4; kf++) {
            int c0 = kf * 16 + t2, c1 = c0 + 8;
            qfh[kf][0] = *(const unsigned*)&ph[r0 + c0];
            qfh[kf][1] = *(const unsigned*)&ph[r1 + c0];
            qfh[kf][2] = *(const unsigned*)&ph[r0 + c1];
            qfh[kf][3] = *(const unsigned*)&ph[r1 + c1];
            qfl[kf][0] = *(const unsigned*)&pl[r0 + c0];
            qfl[kf][1] = *(const unsigned*)&pl[r1 + c0];
            qfl[kf][2] = *(const unsigned*)&pl[r0 + c1];
            qfl[kf][3] = *(const unsigned*)&pl[r1 + c1];
        }
    }

    float o[8][4];
#pragma unroll
    for (int nt = 0; nt < 8; nt++)
#pragma unroll
        for (int i = 0; i < 4; i++) o[nt][i] = 0.f;
    float m0r = MASKVAL, m1r = MASKVAL;
    float l0 = 0.f, l1 = 0.f;

    for (int kt = 0; kt < S_LEN / 64; kt++) {
        __syncthreads();
#pragma unroll
        for (int it = 0; it < 4; it++) {
            int fid = tid + it * 128;
            int row = fid >> 3, cc = (fid & 7) * 8;
            *(uint4*)&kh_s[row][cc] =
                *(const uint4*)&kh[kvb + (size_t)(kt * 64 + row) * HDIM + cc];
            *(uint4*)&kl_s[row][cc] =
                *(const uint4*)&kl[kvb + (size_t)(kt * 64 + row) * HDIM + cc];
            *(uint4*)&vh_s[row][cc] =
                *(const uint4*)&vh[vtb + (size_t)row * S_LEN + kt * 64 + cc];
            *(uint4*)&vl_s[row][cc] =
                *(const uint4*)&vl[vtb + (size_t)row * S_LEN + kt * 64 + cc];
        }
#pragma unroll
        for (int it = 0; it < 2; it++) {
            int fid = tid + it * 128;
            int row = fid >> 2, cc = (fid & 3) * 16;
            *(uint4*)&m_s[row][cc] =
                *(const uint4*)&mask[mrb + (size_t)(qbase + row) * S_LEN + kt * 64 + cc];
        }
        __syncthreads();

        // ---- S = Q K^T ----
        float sacc[8][4];
#pragma unroll
        for (int nt = 0; nt < 8; nt++)
#pragma unroll
            for (int i = 0; i < 4; i++) sacc[nt][i] = 0.f;

#pragma unroll
        for (int nt = 0; nt < 8; nt++) {
            const int nr = nt * 8 + g;
#pragma unroll
            for (int kf = 0; kf < 4; kf++) {
                const int col = kf * 16 + t2;
                unsigned bhf[2], blf[2];
                bhf[0] = *(const unsigned*)&kh_s[nr][col];
                bhf[1] = *(const unsigned*)&kh_s[nr][col + 8];
                blf[0] = *(const unsigned*)&kl_s[nr][col];
                blf[1] = *(const unsigned*)&kl_s[nr][col + 8];
                mma_bf16(sacc[nt], qfh[kf], bhf);
                mma_bf16(sacc[nt], qfh[kf], blf);
                mma_bf16(sacc[nt], qfl[kf], bhf);
            }
        }

        // ---- scale + mask ----
#pragma unroll
        for (int nt = 0; nt < 8; nt++) {
            unsigned short mm0 = *(const unsigned short*)&m_s[wq + g][nt * 8 + t2];
            unsigned short mm1 = *(const unsigned short*)&m_s[wq + g + 8][nt * 8 + t2];
            sacc[nt][0] = (mm0 & 0xFF) ? sacc[nt][0] * 0.125f : MASKVAL;
            sacc[nt][1] = (mm0 >> 8)   ? sacc[nt][1] * 0.125f : MASKVAL;
            sacc[nt][2] = (mm1 & 0xFF) ? sacc[nt][2] * 0.125f : MASKVAL;
            sacc[nt][3] = (mm1 >> 8)   ? sacc[nt][3] * 0.125f : MASKVAL;
        }

        // ---- online softmax ----
        float mx0 = MASKVAL, mx1 = MASKVAL;
#pragma unroll
        for (int nt = 0; nt < 8; nt++) {
            mx0 = fmaxf(mx0, fmaxf(sacc[nt][0], sacc[nt][1]));
            mx1 = fmaxf(mx1, fmaxf(sacc[nt][2], sacc[nt][3]));
        }
        mx0 = fmaxf(mx0, __shfl_xor_sync(0xffffffffu, mx0, 1));
        mx0 = fmaxf(mx0, __shfl_xor_sync(0xffffffffu, mx0, 2));
        mx1 = fmaxf(mx1, __shfl_xor_sync(0xffffffffu, mx1, 1));
        mx1 = fmaxf(mx1, __shfl_xor_sync(0xffffffffu, mx1, 2));

        const float mn0 = fmaxf(m0r, mx0);
        const float mn1 = fmaxf(m1r, mx1);
        const float corr0 = __expf(m0r - mn0);
        const float corr1 = __expf(m1r - mn1);
        m0r = mn0; m1r = mn1;
        l0 *= corr0; l1 *= corr1;
#pragma unroll
        for (int nt = 0; nt < 8; nt++) {
            o[nt][0] *= corr0; o[nt][1] *= corr0;
            o[nt][2] *= corr1; o[nt][3] *= corr1;
        }

        unsigned pfh[8][2], pfl[8][2];
#pragma unroll
        for (int nt = 0; nt < 8; nt++) {
            float p0 = __expf(sacc[nt][0] - mn0);
            float p1 = __expf(sacc[nt][1] - mn0);
            float p2 = __expf(sacc[nt][2] - mn1);
            float p3 = __expf(sacc[nt][3] - mn1);
            l0 += p0 + p1;
            l1 += p2 + p3;
            float h0 = __bfloat162float(__float2bfloat16(p0));
            float h1 = __bfloat162float(__float2bfloat16(p1));
            float h2 = __bfloat162float(__float2bfloat16(p2));
            float h3 = __bfloat162float(__float2bfloat16(p3));
            pfh[nt][0] = pack_bf16x2(h0, h1);
            pfh[nt][1] = pack_bf16x2(h2, h3);
            pfl[nt][0] = pack_bf16x2(p0 - h0, p1 - h1);
            pfl[nt][1] = pack_bf16x2(p2 - h2, p3 - h3);
        }

        // ---- O += P V  (hi/lo on both operands) ----
#pragma unroll
        for (int nt = 0; nt < 8; nt++) {
            const int nr = nt * 8 + g;
#pragma unroll
            for (int kf = 0; kf < 4; kf++) {
                unsigned aph[4] = { pfh[2 * kf][0], pfh[2 * kf][1],
                                    pfh[2 * kf + 1][0], pfh[2 * kf + 1][1] };
                unsigned apl[4] = { pfl[2 * kf][0], pfl[2 * kf][1],
                                    pfl[2 * kf + 1][0], pfl[2 * kf + 1][1] };
                const int col = kf * 16 + t2;
                unsigned bvh[2], bvl[2];
                bvh[0] = *(const unsigned*)&vh_s[nr][col];
                bvh[1] = *(const unsigned*)&vh_s[nr][col + 8];
                bvl[0] = *(const unsigned*)&vl_s[nr][col];
                bvl[1] = *(const unsigned*)&vl_s[nr][col + 8];
                mma_bf16(o[nt], aph, bvh);
                mma_bf16(o[nt], aph, bvl);
                mma_bf16(o[nt], apl, bvh);
            }
        }
    }

    // ---- finalize: write ctx as bf16 hi/lo ----
    l0 += __shfl_xor_sync(0xffffffffu, l0, 1);
    l0 += __shfl_xor_sync(0xffffffffu, l0, 2);
    l1 += __shfl_xor_sync(0xffffffffu, l1, 1);
    l1 += __shfl_xor_sync(0xffffffffu, l1, 2);
    const float rl0 = (l0 > 0.f) ? (1.f / l0) : 0.f;
    const float rl1 = (l1 > 0.f) ? (1.f / l1) : 0.f;

    const int qr0 = qbase + wq + g;
    const size_t o0 = ((size_t)b * S_LEN + qr0) * DMODEL + h * HDIM;
    const size_t o1 = o0 + (size_t)8 * DMODEL;
#pragma unroll
    for (int nt = 0; nt < 8; nt++) {
        float x0 = o[nt][0] * rl0, x1 = o[nt][1] * rl0;
        float x2 = o[nt][2] * rl1, x3 = o[nt][3] * rl1;
        float h0 = __bfloat162float(__float2bfloat16(x0));
        float h1 = __bfloat162float(__float2bfloat16(x1));
        float h2 = __bfloat162float(__float2bfloat16(x2));
        float h3 = __bfloat162float(__float2bfloat16(x3));
        *(unsigned*)&ch[o0 + nt * 8 + t2] = pack_bf16x2(h0, h1);
        *(unsigned*)&cl[o0 + nt * 8 + t2] = pack_bf16x2(x0 - h0, x1 - h1);
        *(unsigned*)&ch[o1 + nt * 8 + t2] = pack_bf16x2(h2, h3);
        *(unsigned*)&cl[o1 + nt * 8 + t2] = pack_bf16x2(x2 - h2, x3 - h3);
    }
}

// ---------------------------------------------------------------------------
extern "C" void kernel_launch(void* const* d_in, const int* in_sizes, int n_in,
                              void* d_out, int out_size)
{
    const float* hidden = (const float*)d_in[0];
    const void*  mask_raw = d_in[1];
    const float* wptr[4] = { (const float*)d_in[2], (const float*)d_in[4],
                             (const float*)d_in[6], (const float*)d_in[8] };
    const float* bptr[4] = { (const float*)d_in[3], (const float*)d_in[5],
                             (const float*)d_in[7], (const float*)d_in[9] };
    float* out = (float*)d_out;

    __nv_bfloat16 *ghh, *ghl, *gwh, *gwl, *gqh, *gql, *gkh, *gkl, *gvh, *gvl, *gch, *gcl;
    unsigned char* gmask;
    cudaGetSymbolAddress((void**)&ghh, g_hh);
    cudaGetSymbolAddress((void**)&ghl, g_hl);
    cudaGetSymbolAddress((void**)&gwh, g_wh);
    cudaGetSymbolAddress((void**)&gwl, g_wl);
    cudaGetSymbolAddress((void**)&gqh, g_qh);
    cudaGetSymbolAddress((void**)&gql, g_ql);
    cudaGetSymbolAddress((void**)&gkh, g_kh);
    cudaGetSymbolAddress((void**)&gkl, g_kl);
    cudaGetSymbolAddress((void**)&gvh, g_vh);
    cudaGetSymbolAddress((void**)&gvl, g_vl);
    cudaGetSymbolAddress((void**)&gch, g_ch);
    cudaGetSymbolAddress((void**)&gcl, g_cl);
    cudaGetSymbolAddress((void**)&gmask, g_mask8);

    // Canonicalize mask
    detect_mask_kernel<<<1, 256>>>((const unsigned char*)mask_raw);
    convert_mask_kernel<<<(MASK_N / 4 + 255) / 256, 256>>>(mask_raw, gmask);

    // hi/lo conversions
    const int nh4 = NTOK * DMODEL / 4;
    cvt_hilo_kernel<<<(nh4 + 255) / 256, 256>>>(hidden, ghh, ghl, nh4);
    const int nw4 = DMODEL * DMODEL / 4;
    for (int i = 0; i < 4; i++)
        cvt_hilo_kernel<<<(nw4 + 255) / 256, 256>>>(
            wptr[i], gwh + (size_t)i * DMODEL * DMODEL, gwl + (size_t)i * DMODEL * DMODEL, nw4);

    dim3 gemmGrid(DMODEL / 128, NTOK / 128);   // (6, 64)
    dim3 gemmBlk(256);

    // QKV projections on tensor cores
    mma_gemm_kernel<<<gemmGrid, gemmBlk>>>(ghh, ghl,
        gwh + 0 * (size_t)DMODEL * DMODEL, gwl + 0 * (size_t)DMODEL * DMODEL,
        bptr[0], nullptr, gqh, gql, 0);
    mma_gemm_kernel<<<gemmGrid, gemmBlk>>>(ghh, ghl,
        gwh + 1 * (size_t)DMODEL * DMODEL, gwl + 1 * (size_t)DMODEL * DMODEL,
        bptr[1], nullptr, gkh, gkl, 0);
    mma_gemm_kernel<<<gemmGrid, gemmBlk>>>(ghh, ghl,
        gwh + 2 * (size_t)DMODEL * DMODEL, gwl + 2 * (size_t)DMODEL * DMODEL,
        bptr[2], nullptr, gvh, gvl, 2);

    // Flash attention -> ctx (bf16 hi/lo)
    dim3 flashGrid(S_LEN / 64, NHEAD, BATCH);
    flash_mma_kernel<<<flashGrid, 128>>>(gqh, gql, gkh, gkl, gvh, gvl, gmask, gch, gcl);

    // Output projection (fp32 out)
    mma_gemm_kernel<<<gemmGrid, gemmBlk>>>(gch, gcl,
        gwh + 3 * (size_t)DMODEL * DMODEL, gwl + 3 * (size_t)DMODEL * DMODEL,
        bptr[3], out, nullptr, nullptr, 1);
}